// round 8
// baseline (speedup 1.0000x reference)
#include <cuda_runtime.h>
#include <math_constants.h>

// Problem constants (fixed by reference: B=4, S=1024, D=512, COMP=4)
#define BATCH   4
#define SEQ     1024
#define DIM     512
#define NCOMP   (SEQ / 4)          // 256
#define STEPS   (SEQ - NCOMP)      // 768
#define NBLK    (SEQ / 32)         // 32 blocks of 32 dot entries

// Mutable working copy + scratch (no allocs allowed in kernel_launch)
__device__ float    g_x[BATCH * SEQ * DIM];
__device__ unsigned g_dotord[BATCH * SEQ];
__device__ int      g_order[BATCH * NCOMP];

// order-preserving float -> uint map (monotonic: a<b  <=>  f2ord(a)<f2ord(b))
__device__ __forceinline__ unsigned f2ord(float f) {
    unsigned u = __float_as_uint(f);
    return (u >> 31) ? ~u : (u | 0x80000000u);
}

// ---------------- copy input to mutable scratch ----------------
__global__ void copy_in_kernel(const float* __restrict__ in) {
    const float4* in4 = (const float4*)in;
    float4* out4 = (float4*)g_x;
    const int n4 = BATCH * SEQ * DIM / 4;
    for (int i = blockIdx.x * blockDim.x + threadIdx.x; i < n4;
         i += gridDim.x * blockDim.x)
        out4[i] = in4[i];
}

// ---------------- initial adjacent dots (one warp per dot, parallel) ----------------
__global__ void init_dots_kernel(const float* __restrict__ in) {
    int w = (blockIdx.x * blockDim.x + threadIdx.x) >> 5;
    int lane = threadIdx.x & 31;
    if (w >= BATCH * SEQ) return;
    int b = w / SEQ, j = w % SEQ;
    unsigned o;
    if (j == SEQ - 1) {
        o = 0u;  // absolute minimum in ord space
    } else {
        const float4* a = (const float4*)(in + ((size_t)b * SEQ + j) * DIM);
        const float4* c = (const float4*)(in + ((size_t)b * SEQ + j + 1) * DIM);
        float acc = 0.f;
        #pragma unroll
        for (int k = 0; k < 4; k++) {
            float4 av = a[k * 32 + lane];
            float4 cv = c[k * 32 + lane];
            acc += av.x * cv.x + av.y * cv.y + av.z * cv.z + av.w * cv.w;
        }
        #pragma unroll
        for (int of = 16; of; of >>= 1) acc += __shfl_xor_sync(0xffffffffu, acc, of);
        o = f2ord(acc);
    }
    if (lane == 0) g_dotord[b * SEQ + j] = o;
}

// ---------------- two-warp merge state machine (one CTA per sample) ----------------
// warp 0 (V): row loads, merge math, dot reduce -> publishes p1o/p2o
// warp 1 (A): link commit, block-max repair, masked rescans, table scan -> (sbv,sbi)
__global__ __launch_bounds__(64)
void merge_kernel() {
    __shared__ unsigned s_dotord[SEQ];   // adjacent dots, ord-mapped (owned by A)
    __shared__ short    s_nxt[SEQ];
    __shared__ short    s_prv[SEQ];
    __shared__ unsigned s_bm[NBLK];      // block maxima (ord)
    __shared__ int      s_bi[NBLK];      // block argmax (global entry index)
    __shared__ unsigned s_res[4];        // {sbv, sbi, p1o, p2o}
    __shared__ int      s_mid0;

    const unsigned FULL = 0xffffffffu;
    const int tid  = threadIdx.x;
    const int lane = tid & 31;
    const int warp = tid >> 5;
    const int b = blockIdx.x;
    float* x = g_x + (size_t)b * SEQ * DIM;

    for (int k = 0; k < SEQ / 64; k++) {
        int i = k * 64 + tid;
        s_dotord[i] = g_dotord[b * SEQ + i];
        s_nxt[i] = (short)((i == SEQ - 1) ? -1 : i + 1);
        s_prv[i] = (short)(i - 1);
    }
    __syncthreads();

    if (warp == 1) {
        // build block maxima
        for (int blk = 0; blk < NBLK; blk++) {
            unsigned d = s_dotord[blk * 32 + lane];
            unsigned m = __reduce_max_sync(FULL, d);
            unsigned bal = __ballot_sync(FULL, d == m);
            if (lane == 0) { s_bm[blk] = m; s_bi[blk] = blk * 32 + __ffs(bal) - 1; }
        }
        __syncwarp();
        // initial global argmax
        unsigned v = s_bm[lane];
        int vb = s_bi[lane];
        unsigned M = __reduce_max_sync(FULL, v);
        unsigned bal = __ballot_sync(FULL, v == M);
        int m0 = __shfl_sync(FULL, vb, __ffs(bal) - 1);
        if (lane == 0) s_mid0 = m0;
    }
    __syncthreads();

    int mid = s_mid0;
    int sb0 = 0, sb1 = 0, sb2 = 0;   // stale blocks (A only)

    for (int t = 0; t < STEPS; t++) {
        // ---- step 1 (both): read links for this merge ----
        const int nxt  = s_nxt[mid];
        const int prev = s_prv[mid];
        const int nn   = s_nxt[nxt];
        __syncthreads();   // bar1: link reads complete before A's link commit

        unsigned p1o = 0u, p2o = 0u;   // V's registers

        if (warp == 0) {
            // ================= V: vector work =================
            const float4* rm = (const float4*)(x + (size_t)mid * DIM);
            const float4* rn = (const float4*)(x + (size_t)nxt * DIM);
            const float4* rp = (prev >= 0) ? (const float4*)(x + (size_t)prev * DIM) : rm;
            const float4* rq = (nn   >= 0) ? (const float4*)(x + (size_t)nn   * DIM) : rm;
            float4 vm[4], vn[4], vp[4], vq[4];
            #pragma unroll
            for (int c = 0; c < 4; c++) {
                vm[c] = rm[c * 32 + lane];
                vn[c] = rn[c * 32 + lane];
                vp[c] = rp[c * 32 + lane];
                vq[c] = rq[c * 32 + lane];
            }
            // merge math (bitwise-identical expressions to the passing kernels)
            float p1 = 0.f, p2 = 0.f;
            float4 nv[4];
            #pragma unroll
            for (int c = 0; c < 4; c++) {
                nv[c].x = 0.5f * (vm[c].x + vn[c].x);
                nv[c].y = 0.5f * (vm[c].y + vn[c].y);
                nv[c].z = 0.5f * (vm[c].z + vn[c].z);
                nv[c].w = 0.5f * (vm[c].w + vn[c].w);
                p1 += vp[c].x * nv[c].x + vp[c].y * nv[c].y + vp[c].z * nv[c].z + vp[c].w * nv[c].w;
                p2 += nv[c].x * vq[c].x + nv[c].y * vq[c].y + nv[c].z * vq[c].z + nv[c].w * vq[c].w;
            }
            float4* wrow = (float4*)(x + (size_t)mid * DIM);
            #pragma unroll
            for (int c = 0; c < 4; c++) wrow[c * 32 + lane] = nv[c];

            #pragma unroll
            for (int o = 16; o; o >>= 1) {
                p1 += __shfl_xor_sync(FULL, p1, o);
                p2 += __shfl_xor_sync(FULL, p2, o);
            }
            p1o = f2ord(p1);
            p2o = f2ord(p2);
            if (lane == 0) { s_res[2] = p1o; s_res[3] = p2o; }
        } else {
            // ================= A: links + argmax table =================
            if (lane == 0) {
                s_nxt[mid] = (short)nn;
                if (nn >= 0) s_prv[nn] = (short)mid;
            }
            // (a) repair stale block maxima from last commit
            {
                unsigned d0 = s_dotord[sb0 * 32 + lane];
                unsigned m0 = __reduce_max_sync(FULL, d0);
                unsigned b0 = __ballot_sync(FULL, d0 == m0);
                unsigned d1 = s_dotord[sb1 * 32 + lane];
                unsigned m1 = __reduce_max_sync(FULL, d1);
                unsigned b1 = __ballot_sync(FULL, d1 == m1);
                unsigned d2 = s_dotord[sb2 * 32 + lane];
                unsigned m2 = __reduce_max_sync(FULL, d2);
                unsigned b2 = __ballot_sync(FULL, d2 == m2);
                if (lane == 0) {
                    s_bm[sb0] = m0; s_bi[sb0] = sb0 * 32 + __ffs(b0) - 1;
                    s_bm[sb1] = m1; s_bi[sb1] = sb1 * 32 + __ffs(b1) - 1;
                    s_bm[sb2] = m2; s_bi[sb2] = sb2 * 32 + __ffs(b2) - 1;
                }
            }
            __syncwarp();
            // (b) masked rescan of the blocks holding {prev, mid, nxt}
            const int dbp = (prev >= 0 ? prev : mid) >> 5;
            const int dbm = mid >> 5;
            const int dbn = nxt >> 5;
            unsigned mP, mM, mN; int iP, iM, iN;
            {
                int e = dbp * 32 + lane;
                unsigned d = s_dotord[e];
                if (e == prev || e == mid || e == nxt) d = 0u;
                mP = __reduce_max_sync(FULL, d);
                unsigned bal = __ballot_sync(FULL, d == mP);
                iP = dbp * 32 + __ffs(bal) - 1;
            }
            {
                int e = dbm * 32 + lane;
                unsigned d = s_dotord[e];
                if (e == prev || e == mid || e == nxt) d = 0u;
                mM = __reduce_max_sync(FULL, d);
                unsigned bal = __ballot_sync(FULL, d == mM);
                iM = dbm * 32 + __ffs(bal) - 1;
            }
            {
                int e = dbn * 32 + lane;
                unsigned d = s_dotord[e];
                if (e == prev || e == mid || e == nxt) d = 0u;
                mN = __reduce_max_sync(FULL, d);
                unsigned bal = __ballot_sync(FULL, d == mN);
                iN = dbn * 32 + __ffs(bal) - 1;
            }
            // (c) scan block maxima, masking the dirty blocks
            unsigned sbv; int sbi;
            {
                unsigned v = s_bm[lane];
                int vb = s_bi[lane];
                if (lane == dbp || lane == dbm || lane == dbn) v = 0u;
                unsigned M = __reduce_max_sync(FULL, v);
                unsigned bal = __ballot_sync(FULL, v == M);
                sbi = __shfl_sync(FULL, vb, __ffs(bal) - 1);
                sbv = M;
            }
            // fold in dirty-block candidates (lex order: value desc, index asc)
            if (mP > sbv || (mP == sbv && iP < sbi)) { sbv = mP; sbi = iP; }
            if (mM > sbv || (mM == sbv && iM < sbi)) { sbv = mM; sbi = iM; }
            if (mN > sbv || (mN == sbv && iN < sbi)) { sbv = mN; sbi = iN; }
            if (lane == 0) { s_res[0] = sbv; s_res[1] = (unsigned)sbi; }
            sb0 = dbp; sb1 = dbm; sb2 = dbn;
        }
        __syncthreads();   // bar2: exchange results

        // ---- combine (both warps, identical integer ops -> identical result) ----
        const unsigned sbv = s_res[0];
        const int      sbi = (int)s_res[1];
        if (warp == 1) { p1o = s_res[2]; p2o = s_res[3]; }
        int newmid = sbi; unsigned newbv = sbv;
        if (prev >= 0 && (p1o > newbv || (p1o == newbv && prev < newmid))) { newbv = p1o; newmid = prev; }
        if (nn   >= 0 && (p2o > newbv || (p2o == newbv && mid  < newmid))) { newbv = p2o; newmid = mid; }

        // ---- A commits dot-table entries (read by A only, after next bar1) ----
        if (warp == 1 && lane == 0) {
            if (prev >= 0) s_dotord[prev] = p1o;
            s_dotord[mid] = (nn >= 0) ? p2o : 0u;
            s_dotord[nxt] = 0u;
        }
        mid = newmid;
    }

    __syncthreads();
    // survivor order (head 0 is never removed — removed rows are always 'nxt')
    if (tid == 0) {
        int idx = 0;
        for (int c = 0; c < NCOMP; c++) { g_order[b * NCOMP + c] = idx; idx = s_nxt[idx]; }
    }
}

// ---------------- gather survivors to output (parallel) ----------------
__global__ void gather_kernel(float* __restrict__ out) {
    int r = blockIdx.x;                 // 0 .. BATCH*NCOMP-1
    int b = r / NCOMP;
    int src = g_order[r];
    const float4* s = (const float4*)(g_x + ((size_t)b * SEQ + src) * DIM);
    float4* d = (float4*)(out + (size_t)r * DIM);
    d[threadIdx.x] = s[threadIdx.x];    // 128 threads x float4 = 512 floats
}

extern "C" void kernel_launch(void* const* d_in, const int* in_sizes, int n_in,
                              void* d_out, int out_size) {
    const float* x = (const float*)d_in[0];
    float* out = (float*)d_out;
    copy_in_kernel<<<256, 256>>>(x);
    init_dots_kernel<<<(BATCH * SEQ * 32) / 256, 256>>>(x);
    merge_kernel<<<BATCH, 64>>>();
    gather_kernel<<<BATCH * NCOMP, 128>>>(out);
}

// round 10
// speedup vs baseline: 1.9973x; 1.9973x over previous
#include <cuda_runtime.h>
#include <math_constants.h>

// Problem constants (fixed by reference: B=4, S=1024, D=512, COMP=4)
#define BATCH   4
#define SEQ     1024
#define DIM     512
#define NCOMP   (SEQ / 4)          // 256
#define STEPS   (SEQ - NCOMP)      // 768
#define NBLK    (SEQ / 32)         // 32 blocks of 32 dot entries

// Mutable working copy + scratch (no allocs allowed in kernel_launch)
__device__ float    g_x[BATCH * SEQ * DIM];
__device__ unsigned g_dotord[BATCH * SEQ];
__device__ int      g_order[BATCH * NCOMP];

// order-preserving float -> uint map (monotonic: a<b  <=>  f2ord(a)<f2ord(b))
__device__ __forceinline__ unsigned f2ord(float f) {
    unsigned u = __float_as_uint(f);
    return (u >> 31) ? ~u : (u | 0x80000000u);
}

// ---------------- copy input to mutable scratch ----------------
__global__ void copy_in_kernel(const float* __restrict__ in) {
    const float4* in4 = (const float4*)in;
    float4* out4 = (float4*)g_x;
    const int n4 = BATCH * SEQ * DIM / 4;
    for (int i = blockIdx.x * blockDim.x + threadIdx.x; i < n4;
         i += gridDim.x * blockDim.x)
        out4[i] = in4[i];
}

// ---------------- initial adjacent dots (one warp per dot, parallel) ----------------
__global__ void init_dots_kernel(const float* __restrict__ in) {
    int w = (blockIdx.x * blockDim.x + threadIdx.x) >> 5;
    int lane = threadIdx.x & 31;
    if (w >= BATCH * SEQ) return;
    int b = w / SEQ, j = w % SEQ;
    unsigned o;
    if (j == SEQ - 1) {
        o = 0u;  // absolute minimum in ord space
    } else {
        const float4* a = (const float4*)(in + ((size_t)b * SEQ + j) * DIM);
        const float4* c = (const float4*)(in + ((size_t)b * SEQ + j + 1) * DIM);
        float acc = 0.f;
        #pragma unroll
        for (int k = 0; k < 4; k++) {
            float4 av = a[k * 32 + lane];
            float4 cv = c[k * 32 + lane];
            acc += av.x * cv.x + av.y * cv.y + av.z * cv.z + av.w * cv.w;
        }
        #pragma unroll
        for (int of = 16; of; of >>= 1) acc += __shfl_xor_sync(0xffffffffu, acc, of);
        o = f2ord(acc);
    }
    if (lane == 0) g_dotord[b * SEQ + j] = o;
}

// ---------------- single-warp merge state machine (one per sample) ----------------
__global__ __launch_bounds__(32)
void merge_kernel() {
    __shared__ unsigned s_dotord[SEQ];   // adjacent dots, ord-mapped
    __shared__ unsigned s_lnk[SEQ];      // packed links: (prv&0xffff)<<16 | (nxt&0xffff)
    __shared__ unsigned s_bm[NBLK];      // block maxima (ord)
    __shared__ int      s_bi[NBLK];      // block argmax (global entry index)

    const unsigned FULL = 0xffffffffu;
    const int lane = threadIdx.x;
    const int b = blockIdx.x;
    float* x = g_x + (size_t)b * SEQ * DIM;

    #pragma unroll
    for (int k = 0; k < SEQ / 32; k++) {
        int i = k * 32 + lane;
        s_dotord[i] = g_dotord[b * SEQ + i];
        unsigned nx = (i == SEQ - 1) ? 0xffffu : (unsigned)(i + 1);
        unsigned pv = (unsigned)(i - 1) & 0xffffu;
        s_lnk[i] = (pv << 16) | nx;
    }
    __syncwarp();

    // build block maxima
    for (int blk = 0; blk < NBLK; blk++) {
        unsigned d = s_dotord[blk * 32 + lane];
        unsigned m = __reduce_max_sync(FULL, d);
        unsigned bal = __ballot_sync(FULL, d == m);
        if (lane == 0) { s_bm[blk] = m; s_bi[blk] = blk * 32 + __ffs(bal) - 1; }
    }
    __syncwarp();

    // initial global argmax
    int mid;
    {
        unsigned v = s_bm[lane];
        int vb = s_bi[lane];
        unsigned M = __reduce_max_sync(FULL, v);
        unsigned bal = __ballot_sync(FULL, v == M);
        int wl = __ffs(bal) - 1;
        mid = __shfl_sync(FULL, vb, wl);
    }

    int sb0 = 0, sb1 = 0, sb2 = 0;   // stale blocks (bm not yet refreshed)

    for (int t = 0; t < STEPS; t++) {
        const unsigned lm = s_lnk[mid];
        const int nxt  = (int)(short)(lm & 0xffffu);
        const int prev = (int)(short)(lm >> 16);
        const int nn   = (int)(short)(s_lnk[nxt] & 0xffffu);

        // ---- issue all row loads up front (L2-latency shadow) ----
        const float4* rm = (const float4*)(x + (size_t)mid * DIM);
        const float4* rn = (const float4*)(x + (size_t)nxt * DIM);
        const float4* rp = (prev >= 0) ? (const float4*)(x + (size_t)prev * DIM) : rm;
        const float4* rq = (nn   >= 0) ? (const float4*)(x + (size_t)nn   * DIM) : rm;
        float4 vm[4], vn[4], vp[4], vq[4];
        #pragma unroll
        for (int c = 0; c < 4; c++) {
            vm[c] = rm[c * 32 + lane];
            vn[c] = rn[c * 32 + lane];
            vp[c] = rp[c * 32 + lane];
            vq[c] = rq[c * 32 + lane];
        }

        // ---- (a) repair stale block maxima from last commit (under shadow) ----
        {
            unsigned d0 = s_dotord[sb0 * 32 + lane];
            unsigned m0 = __reduce_max_sync(FULL, d0);
            unsigned b0 = __ballot_sync(FULL, d0 == m0);
            unsigned d1 = s_dotord[sb1 * 32 + lane];
            unsigned m1 = __reduce_max_sync(FULL, d1);
            unsigned b1 = __ballot_sync(FULL, d1 == m1);
            unsigned d2 = s_dotord[sb2 * 32 + lane];
            unsigned m2 = __reduce_max_sync(FULL, d2);
            unsigned b2 = __ballot_sync(FULL, d2 == m2);
            if (lane == 0) {
                s_bm[sb0] = m0; s_bi[sb0] = sb0 * 32 + __ffs(b0) - 1;
                s_bm[sb1] = m1; s_bi[sb1] = sb1 * 32 + __ffs(b1) - 1;
                s_bm[sb2] = m2; s_bi[sb2] = sb2 * 32 + __ffs(b2) - 1;
            }
        }
        __syncwarp();

        // ---- (b) masked rescan of the blocks holding {prev, mid, nxt} ----
        const int dbp = (prev >= 0 ? prev : mid) >> 5;
        const int dbm = mid >> 5;
        const int dbn = nxt >> 5;
        unsigned mP, mM, mN; int iP, iM, iN;
        {
            int e = dbp * 32 + lane;
            unsigned d = s_dotord[e];
            if (e == prev || e == mid || e == nxt) d = 0u;
            mP = __reduce_max_sync(FULL, d);
            unsigned bal = __ballot_sync(FULL, d == mP);
            iP = dbp * 32 + __ffs(bal) - 1;
        }
        {
            int e = dbm * 32 + lane;
            unsigned d = s_dotord[e];
            if (e == prev || e == mid || e == nxt) d = 0u;
            mM = __reduce_max_sync(FULL, d);
            unsigned bal = __ballot_sync(FULL, d == mM);
            iM = dbm * 32 + __ffs(bal) - 1;
        }
        {
            int e = dbn * 32 + lane;
            unsigned d = s_dotord[e];
            if (e == prev || e == mid || e == nxt) d = 0u;
            mN = __reduce_max_sync(FULL, d);
            unsigned bal = __ballot_sync(FULL, d == mN);
            iN = dbn * 32 + __ffs(bal) - 1;
        }

        // ---- (c) scan block maxima, masking the dirty blocks ----
        unsigned sbv; int sbi;
        {
            unsigned v = s_bm[lane];
            int vb = s_bi[lane];
            if (lane == dbp || lane == dbm || lane == dbn) v = 0u;
            unsigned M = __reduce_max_sync(FULL, v);
            unsigned bal = __ballot_sync(FULL, v == M);
            int wl = __ffs(bal) - 1;
            sbi = __shfl_sync(FULL, vb, wl);
            sbv = M;
        }
        // fold in dirty-block candidates (lex order: value desc, index asc)
        if (mP > sbv || (mP == sbv && iP < sbi)) { sbv = mP; sbi = iP; }
        if (mM > sbv || (mM == sbv && iM < sbi)) { sbv = mM; sbi = iM; }
        if (mN > sbv || (mN == sbv && iN < sbi)) { sbv = mN; sbi = iN; }

        // ---- merge math (same per-lane expressions as the passing kernels) ----
        float p1 = 0.f, p2 = 0.f;
        float4 nv[4];
        #pragma unroll
        for (int c = 0; c < 4; c++) {
            nv[c].x = 0.5f * (vm[c].x + vn[c].x);
            nv[c].y = 0.5f * (vm[c].y + vn[c].y);
            nv[c].z = 0.5f * (vm[c].z + vn[c].z);
            nv[c].w = 0.5f * (vm[c].w + vn[c].w);
            p1 += vp[c].x * nv[c].x + vp[c].y * nv[c].y + vp[c].z * nv[c].z + vp[c].w * nv[c].w;
            p2 += nv[c].x * vq[c].x + nv[c].y * vq[c].y + nv[c].z * vq[c].z + nv[c].w * vq[c].w;
        }
        float4* wrow = (float4*)(x + (size_t)mid * DIM);
        #pragma unroll
        for (int c = 0; c < 4; c++) wrow[c * 32 + lane] = nv[c];

        // ---- paired half-warp reduce: even lanes carry Σp1, odd lanes Σp2 ----
        {
            float t1 = __shfl_xor_sync(FULL, p1, 1);
            float t2 = __shfl_xor_sync(FULL, p2, 1);
            float v = (lane & 1) ? (p2 + t2) : (p1 + t1);
            #pragma unroll
            for (int o = 2; o <= 16; o <<= 1)
                v += __shfl_xor_sync(FULL, v, o);
            p1 = __shfl_sync(FULL, v, 0);
            p2 = __shfl_sync(FULL, v, 1);
        }

        // ---- final selection: spec winner vs the two refreshed entries ----
        const unsigned p1o = f2ord(p1);
        const unsigned p2o = f2ord(p2);
        int newmid = sbi; unsigned newbv = sbv;
        if (prev >= 0 && (p1o > newbv || (p1o == newbv && prev < newmid))) { newbv = p1o; newmid = prev; }
        if (nn   >= 0 && (p2o > newbv || (p2o == newbv && mid  < newmid))) { newbv = p2o; newmid = mid; }

        // ---- commit table + links; mark blocks stale for next-step repair ----
        if (lane == 0) {
            if (prev >= 0) s_dotord[prev] = p1o;
            s_dotord[mid] = (nn >= 0) ? p2o : 0u;
            s_dotord[nxt] = 0u;
            // link mid -> nn (keep mid's prv field)
            s_lnk[mid] = (lm & 0xffff0000u) | ((unsigned)nn & 0xffffu);
            if (nn >= 0)
                s_lnk[nn] = (((unsigned)mid & 0xffffu) << 16) | (s_lnk[nn] & 0xffffu);
        }
        sb0 = dbp; sb1 = dbm; sb2 = dbn;
        __syncwarp();

        mid = newmid;
    }

    // survivor order (head 0 is never removed — removed rows are always 'nxt')
    if (lane == 0) {
        int idx = 0;
        for (int c = 0; c < NCOMP; c++) {
            g_order[b * NCOMP + c] = idx;
            idx = (int)(short)(s_lnk[idx] & 0xffffu);
        }
    }
}

// ---------------- gather survivors to output (parallel) ----------------
__global__ void gather_kernel(float* __restrict__ out) {
    int r = blockIdx.x;                 // 0 .. BATCH*NCOMP-1
    int b = r / NCOMP;
    int src = g_order[r];
    const float4* s = (const float4*)(g_x + ((size_t)b * SEQ + src) * DIM);
    float4* d = (float4*)(out + (size_t)r * DIM);
    d[threadIdx.x] = s[threadIdx.x];    // 128 threads x float4 = 512 floats
}

extern "C" void kernel_launch(void* const* d_in, const int* in_sizes, int n_in,
                              void* d_out, int out_size) {
    const float* x = (const float*)d_in[0];
    float* out = (float*)d_out;
    copy_in_kernel<<<256, 256>>>(x);
    init_dots_kernel<<<(BATCH * SEQ * 32) / 256, 256>>>(x);
    merge_kernel<<<BATCH, 32>>>();
    gather_kernel<<<BATCH * NCOMP, 128>>>(out);
}